// round 1
// baseline (speedup 1.0000x reference)
#include <cuda_runtime.h>
#include <cstdint>

// Problem constants
constexpr int T  = 2048;
constexpr int B  = 4;
constexpr int C  = 1024;
constexpr int H  = 16;
constexpr int DK = 64;
constexpr int N  = T * B;     // 8192 tokens
constexpr int BH = B * H;     // 64

// Scratch (static device globals — no allocation allowed)
__device__ float g_Q[(size_t)BH * T * DK];   // (b*H+h, t, d)
__device__ float g_K[(size_t)BH * T * DK];
__device__ float g_V[(size_t)BH * T * DK];
__device__ float g_X2[(size_t)N * C];        // attention out, rows n=t*B+b
__device__ unsigned char g_mask[B * T];      // normalized: 1 = masked
__device__ int g_maskKind;                   // 0=byte, 1=int32, 2=float32

// ---------------------------------------------------------------------------
// Mask dtype detection: read only the first B*T bytes (valid for all dtypes).
// int32 0/1 little-endian: bytes at p%4 in {1,2,3} are zero.
// float32 0.0/1.0: bytes at p%4 in {0,1,2} are zero, p%4==3 is 0x00/0x3F.
// bool/int8 random: ~half the bytes at p%4 in {1,2} are nonzero.
// ---------------------------------------------------------------------------
__global__ void mask_detect_kernel(const unsigned char* __restrict__ raw) {
    __shared__ int c12, c3;
    if (threadIdx.x == 0) { c12 = 0; c3 = 0; }
    __syncthreads();
    int l12 = 0, l3 = 0;
    for (int p = threadIdx.x; p < B * T; p += 256) {
        unsigned char v = raw[p];
        if (v) {
            int m = p & 3;
            if (m == 1 || m == 2) l12++;
            else if (m == 3) l3++;
        }
    }
    if (l12) atomicAdd(&c12, l12);
    if (l3)  atomicAdd(&c3, l3);
    __syncthreads();
    if (threadIdx.x == 0)
        g_maskKind = (c12 > 0) ? 0 : ((c3 > 0) ? 2 : 1);
}

__global__ void mask_prep_kernel(const void* __restrict__ raw) {
    int i = blockIdx.x * blockDim.x + threadIdx.x;
    if (i >= B * T) return;
    int kind = g_maskKind;
    unsigned char r;
    if (kind == 0)      r = (((const unsigned char*)raw)[i] != 0);
    else if (kind == 1) r = (((const int*)raw)[i] != 0);
    else                r = (((const float*)raw)[i] != 0.0f);
    g_mask[i] = r;
}

// ---------------------------------------------------------------------------
// SIMT GEMM body: Y = X @ W^T + bias, X:[N,1024] row-major, W:[1024,1024]
// 128x128 tile, BK=16, 256 threads, 8x8 microtile.
// MODE 0: scatter into (b*H+h, t, d) layout.  MODE 1: Y[r*1024 + o].
// ---------------------------------------------------------------------------
template <int MODE>
__device__ __forceinline__ void gemm_body(
    const float* __restrict__ X, const float* __restrict__ W,
    const float* __restrict__ bias, float* __restrict__ Y)
{
    __shared__ float As[16][128];   // k-major
    __shared__ float Bs[16][128];
    const int tid = threadIdx.x;
    const int tx = tid & 15;
    const int ty = tid >> 4;
    const int rowBase = blockIdx.y * 128;
    const int colBase = blockIdx.x * 128;

    float acc[8][8];
#pragma unroll
    for (int i = 0; i < 8; i++)
#pragma unroll
        for (int j = 0; j < 8; j++) acc[i][j] = 0.0f;

    for (int k0 = 0; k0 < 1024; k0 += 16) {
#pragma unroll
        for (int e = 0; e < 2; e++) {
            int id = tid + e * 256;
            int r  = id >> 2;
            int c  = (id & 3) << 2;
            float4 va = *reinterpret_cast<const float4*>(&X[(size_t)(rowBase + r) * 1024 + k0 + c]);
            As[c + 0][r] = va.x; As[c + 1][r] = va.y; As[c + 2][r] = va.z; As[c + 3][r] = va.w;
            float4 vb = *reinterpret_cast<const float4*>(&W[(size_t)(colBase + r) * 1024 + k0 + c]);
            Bs[c + 0][r] = vb.x; Bs[c + 1][r] = vb.y; Bs[c + 2][r] = vb.z; Bs[c + 3][r] = vb.w;
        }
        __syncthreads();
#pragma unroll
        for (int kk = 0; kk < 16; kk++) {
            float4 a0 = *reinterpret_cast<const float4*>(&As[kk][(ty << 2)]);
            float4 a1 = *reinterpret_cast<const float4*>(&As[kk][64 + (ty << 2)]);
            float4 b0 = *reinterpret_cast<const float4*>(&Bs[kk][(tx << 2)]);
            float4 b1 = *reinterpret_cast<const float4*>(&Bs[kk][64 + (tx << 2)]);
            float a[8] = {a0.x, a0.y, a0.z, a0.w, a1.x, a1.y, a1.z, a1.w};
            float b[8] = {b0.x, b0.y, b0.z, b0.w, b1.x, b1.y, b1.z, b1.w};
#pragma unroll
            for (int i = 0; i < 8; i++)
#pragma unroll
                for (int j = 0; j < 8; j++)
                    acc[i][j] += a[i] * b[j];
        }
        __syncthreads();
    }

#pragma unroll
    for (int ic = 0; ic < 2; ic++)
#pragma unroll
        for (int i = 0; i < 4; i++) {
            int r = rowBase + ic * 64 + (ty << 2) + i;
#pragma unroll
            for (int jc = 0; jc < 2; jc++) {
                int o0 = colBase + jc * 64 + (tx << 2);
                float4 v;
                v.x = acc[ic * 4 + i][jc * 4 + 0] + bias[o0 + 0];
                v.y = acc[ic * 4 + i][jc * 4 + 1] + bias[o0 + 1];
                v.z = acc[ic * 4 + i][jc * 4 + 2] + bias[o0 + 2];
                v.w = acc[ic * 4 + i][jc * 4 + 3] + bias[o0 + 3];
                if (MODE == 0) {
                    int bb = r & 3;      // n % B
                    int t  = r >> 2;     // n / B
                    int hh = o0 >> 6;
                    int d  = o0 & 63;
                    *reinterpret_cast<float4*>(
                        &Y[((size_t)((bb << 4) + hh) * T + t) * DK + d]) = v;
                } else {
                    *reinterpret_cast<float4*>(&Y[(size_t)r * 1024 + o0]) = v;
                }
            }
        }
}

__global__ void __launch_bounds__(256) qkv_kernel(
    const float* __restrict__ q, const float* __restrict__ k, const float* __restrict__ v,
    const float* __restrict__ Wq, const float* __restrict__ Wk, const float* __restrict__ Wv,
    const float* __restrict__ bq, const float* __restrict__ bk, const float* __restrict__ bv)
{
    const float* X; const float* W; const float* bias; float* Y;
    if (blockIdx.z == 0)      { X = q; W = Wq; bias = bq; Y = g_Q; }
    else if (blockIdx.z == 1) { X = k; W = Wk; bias = bk; Y = g_K; }
    else                      { X = v; W = Wv; bias = bv; Y = g_V; }
    gemm_body<0>(X, W, bias, Y);
}

__global__ void __launch_bounds__(256) outproj_kernel(
    const float* __restrict__ Wo, const float* __restrict__ bo, float* __restrict__ out)
{
    gemm_body<1>(g_X2, Wo, bo, out);
}

// ---------------------------------------------------------------------------
// Flash attention: one block per (bh, 64-row Q tile). 256 threads (16x16),
// each owns a 4x4 S/P microtile and a 4x4 O microtile.
// smem = Qs(16K) + KP(16K, K-tile reused for P) + Vs(16K) = 48 KB exactly.
// ---------------------------------------------------------------------------
__global__ void __launch_bounds__(256) attn_kernel()
{
    __shared__ float Qs[DK][64];   // [d][q]  (d-major for conflict-free S GEMM)
    __shared__ float KP[64][64];   // phase 1: K [d][kv];  phase 2: P [q][kv]
    __shared__ float Vs[64][DK];   // [kv][d]

    const int tid = threadIdx.x;
    const int tx  = tid & 15;
    const int ty  = tid >> 4;
    const int bh  = blockIdx.y;
    const int bb  = bh >> 4;       // batch
    const int h   = bh & 15;       // head
    const int q0  = blockIdx.x * 64;

    const float* __restrict__ Qg = g_Q + (size_t)bh * T * DK;
    const float* __restrict__ Kg = g_K + (size_t)bh * T * DK;
    const float* __restrict__ Vg = g_V + (size_t)bh * T * DK;

    // Load Q tile transposed -> Qs[d][q]
#pragma unroll
    for (int e = 0; e < 4; e++) {
        int id = tid + e * 256;
        int r  = id >> 4;
        int d  = (id & 15) << 2;
        float4 v = *reinterpret_cast<const float4*>(&Qg[(size_t)(q0 + r) * DK + d]);
        Qs[d + 0][r] = v.x; Qs[d + 1][r] = v.y; Qs[d + 2][r] = v.z; Qs[d + 3][r] = v.w;
    }

    float m_r[4], l_r[4], o_r[4][4];
#pragma unroll
    for (int i = 0; i < 4; i++) {
        m_r[i] = -1e30f;
        l_r[i] = 0.0f;
#pragma unroll
        for (int j = 0; j < 4; j++) o_r[i][j] = 0.0f;
    }

    for (int kv0 = 0; kv0 < T; kv0 += 64) {
        __syncthreads();   // prior PV done reading KP/Vs; also covers Q-tile stores
        // Load K (transposed) and V tiles
#pragma unroll
        for (int e = 0; e < 4; e++) {
            int id = tid + e * 256;
            int r  = id >> 4;
            int d  = (id & 15) << 2;
            float4 kv = *reinterpret_cast<const float4*>(&Kg[(size_t)(kv0 + r) * DK + d]);
            KP[d + 0][r] = kv.x; KP[d + 1][r] = kv.y; KP[d + 2][r] = kv.z; KP[d + 3][r] = kv.w;
            float4 vv = *reinterpret_cast<const float4*>(&Vg[(size_t)(kv0 + r) * DK + d]);
            *reinterpret_cast<float4*>(&Vs[r][d]) = vv;
        }
        __syncthreads();

        // S = Q @ K^T (per-thread 4x4)
        float s[4][4];
#pragma unroll
        for (int i = 0; i < 4; i++)
#pragma unroll
            for (int j = 0; j < 4; j++) s[i][j] = 0.0f;
#pragma unroll 8
        for (int d = 0; d < DK; d++) {
            float4 a = *reinterpret_cast<const float4*>(&Qs[d][(ty << 2)]);
            float4 b = *reinterpret_cast<const float4*>(&KP[d][(tx << 2)]);
            s[0][0] += a.x * b.x; s[0][1] += a.x * b.y; s[0][2] += a.x * b.z; s[0][3] += a.x * b.w;
            s[1][0] += a.y * b.x; s[1][1] += a.y * b.y; s[1][2] += a.y * b.z; s[1][3] += a.y * b.w;
            s[2][0] += a.z * b.x; s[2][1] += a.z * b.y; s[2][2] += a.z * b.z; s[2][3] += a.z * b.w;
            s[3][0] += a.w * b.x; s[3][1] += a.w * b.y; s[3][2] += a.w * b.z; s[3][3] += a.w * b.w;
        }

        // Mask + scale (reference: mask -> -inf, then clip to -1e8)
        uchar4 mk = *reinterpret_cast<const uchar4*>(&g_mask[bb * T + kv0 + (tx << 2)]);
        unsigned char mka[4] = {mk.x, mk.y, mk.z, mk.w};
#pragma unroll
        for (int i = 0; i < 4; i++)
#pragma unroll
            for (int j = 0; j < 4; j++)
                s[i][j] = mka[j] ? -1e8f : s[i][j] * 0.125f;

        // Online softmax over 16 tx lanes (lane = (ty&1)*16 + tx; xor<16 stays in group)
#pragma unroll
        for (int i = 0; i < 4; i++) {
            float mt = fmaxf(fmaxf(s[i][0], s[i][1]), fmaxf(s[i][2], s[i][3]));
#pragma unroll
            for (int w = 1; w < 16; w <<= 1)
                mt = fmaxf(mt, __shfl_xor_sync(0xffffffffu, mt, w));
            float mn   = fmaxf(m_r[i], mt);
            float corr = __expf(m_r[i] - mn);
            m_r[i] = mn;
            float rs = 0.0f;
#pragma unroll
            for (int j = 0; j < 4; j++) {
                float p = __expf(s[i][j] - mn);
                s[i][j] = p;
                rs += p;
            }
#pragma unroll
            for (int w = 1; w < 16; w <<= 1)
                rs += __shfl_xor_sync(0xffffffffu, rs, w);
            l_r[i] = l_r[i] * corr + rs;
#pragma unroll
            for (int j = 0; j < 4; j++) o_r[i][j] *= corr;
        }

        __syncthreads();   // all threads done reading KP as K
        // Write P -> KP[q][kv]
#pragma unroll
        for (int i = 0; i < 4; i++) {
            float4 pv = make_float4(s[i][0], s[i][1], s[i][2], s[i][3]);
            *reinterpret_cast<float4*>(&KP[(ty << 2) + i][(tx << 2)]) = pv;
        }
        __syncthreads();

        // O += P @ V
#pragma unroll 8
        for (int k = 0; k < 64; k++) {
            float4 bv = *reinterpret_cast<const float4*>(&Vs[k][(tx << 2)]);
#pragma unroll
            for (int i = 0; i < 4; i++) {
                float a = KP[(ty << 2) + i][k];
                o_r[i][0] += a * bv.x;
                o_r[i][1] += a * bv.y;
                o_r[i][2] += a * bv.z;
                o_r[i][3] += a * bv.w;
            }
        }
    }

    // Epilogue: O /= l, store to X2 rows n = t*B + b, cols h*64 + d
#pragma unroll
    for (int i = 0; i < 4; i++) {
        float inv = 1.0f / l_r[i];
        int t = q0 + (ty << 2) + i;
        float4 ov = make_float4(o_r[i][0] * inv, o_r[i][1] * inv,
                                o_r[i][2] * inv, o_r[i][3] * inv);
        *reinterpret_cast<float4*>(
            &g_X2[(size_t)(t * B + bb) * C + h * DK + (tx << 2)]) = ov;
    }
}

// ---------------------------------------------------------------------------
extern "C" void kernel_launch(void* const* d_in, const int* in_sizes, int n_in,
                              void* d_out, int out_size)
{
    const float* q    = (const float*)d_in[0];
    const float* k    = (const float*)d_in[1];
    const float* v    = (const float*)d_in[2];
    const void*  mask = d_in[3];
    const float* Wq   = (const float*)d_in[4];
    const float* bq   = (const float*)d_in[5];
    const float* Wk   = (const float*)d_in[6];
    const float* bk   = (const float*)d_in[7];
    const float* Wv   = (const float*)d_in[8];
    const float* bv   = (const float*)d_in[9];
    const float* Wo   = (const float*)d_in[10];
    const float* bo   = (const float*)d_in[11];
    float* out = (float*)d_out;

    mask_detect_kernel<<<1, 256>>>((const unsigned char*)mask);
    mask_prep_kernel<<<(B * T + 255) / 256, 256>>>(mask);

    dim3 gqkv(C / 128, N / 128, 3);
    qkv_kernel<<<gqkv, 256>>>(q, k, v, Wq, Wk, Wv, bq, bk, bv);

    attn_kernel<<<dim3(T / 64, BH), 256>>>();

    dim3 gout(C / 128, N / 128);
    outproj_kernel<<<gout, 256>>>(Wo, bo, out);
}

// round 15
// speedup vs baseline: 1.0250x; 1.0250x over previous
#include <cuda_runtime.h>
#include <cstdint>

// Problem constants
constexpr int T  = 2048;
constexpr int B  = 4;
constexpr int C  = 1024;
constexpr int H  = 16;
constexpr int DK = 64;
constexpr int NTOK = T * B;   // 8192 tokens
constexpr int BH = B * H;     // 64

// Scratch (static device globals — no allocation allowed)
__device__ float g_Q[(size_t)BH * T * DK];
__device__ float g_K[(size_t)BH * T * DK];
__device__ float g_V[(size_t)BH * T * DK];
__device__ float g_X2[(size_t)NTOK * C];
__device__ unsigned char g_mask[B * T];
__device__ int g_maskKind;

// ===========================================================================
// Packed f32x2 ops (sm_100-family PTX; compile-validated on this harness's
// compute_103 target in R12 — only tcgen05 was rejected)
// ===========================================================================
__device__ __forceinline__ void ffma2(unsigned long long& d,
                                      unsigned long long a, unsigned long long b) {
    asm("fma.rn.f32x2 %0, %1, %2, %0;" : "+l"(d) : "l"(a), "l"(b));
}
__device__ __forceinline__ void mul2(unsigned long long& d, unsigned long long a) {
    asm("mul.rn.f32x2 %0, %0, %1;" : "+l"(d) : "l"(a));
}
__device__ __forceinline__ unsigned long long bcast2(float x) {
    unsigned long long r;
    asm("mov.b64 %0, {%1, %1};" : "=l"(r) : "r"(__float_as_uint(x)));
    return r;
}
__device__ __forceinline__ void unpack2(unsigned long long v, float& lo, float& hi) {
    uint32_t a, b;
    asm("mov.b64 {%0, %1}, %2;" : "=r"(a), "=r"(b) : "l"(v));
    lo = __uint_as_float(a);
    hi = __uint_as_float(b);
}

// ===========================================================================
// Mask dtype detection + normalization (hardware-verified in R1)
// ===========================================================================
__global__ void mask_detect_kernel(const unsigned char* __restrict__ raw) {
    __shared__ int c12, c3;
    if (threadIdx.x == 0) { c12 = 0; c3 = 0; }
    __syncthreads();
    int l12 = 0, l3 = 0;
    for (int p = threadIdx.x; p < B * T; p += 256) {
        unsigned char v = raw[p];
        if (v) {
            int m = p & 3;
            if (m == 1 || m == 2) l12++;
            else if (m == 3) l3++;
        }
    }
    if (l12) atomicAdd(&c12, l12);
    if (l3)  atomicAdd(&c3, l3);
    __syncthreads();
    if (threadIdx.x == 0)
        g_maskKind = (c12 > 0) ? 0 : ((c3 > 0) ? 2 : 1);
}

__global__ void mask_prep_kernel(const void* __restrict__ raw) {
    int i = blockIdx.x * blockDim.x + threadIdx.x;
    if (i >= B * T) return;
    int kind = g_maskKind;
    unsigned char r;
    if (kind == 0)      r = (((const unsigned char*)raw)[i] != 0);
    else if (kind == 1) r = (((const int*)raw)[i] != 0);
    else                r = (((const float*)raw)[i] != 0.0f);
    g_mask[i] = r;
}

// ===========================================================================
// SIMT GEMM (R1-verified tiling) with FFMA2 inner product.
// Y = X @ W^T + bias. 128x128 tile, BK=16, 256 threads, 8x8 microtile.
// Per kk step: 8 bcast (alu pipe) + 32 FFMA2 instead of 64 FFMA.
// MODE 0: scatter into (b*H+h, t, d).  MODE 1: Y[r*1024 + o].
// ===========================================================================
template <int MODE>
__device__ __forceinline__ void gemm_body(
    const float* __restrict__ X, const float* __restrict__ W,
    const float* __restrict__ bias, float* __restrict__ Y)
{
    __shared__ float As[16][128];   // k-major
    __shared__ float Bs[16][128];
    const int tid = threadIdx.x;
    const int tx = tid & 15;
    const int ty = tid >> 4;
    const int rowBase = blockIdx.y * 128;
    const int colBase = blockIdx.x * 128;

    // acc2[ii][p]: row ii (0..7), packed column pairs:
    // p=0 -> cols (tx*4+0, +1), p=1 -> (+2,+3), p=2/3 -> same at col+64
    unsigned long long acc2[8][4];
#pragma unroll
    for (int i = 0; i < 8; i++)
#pragma unroll
        for (int p = 0; p < 4; p++) acc2[i][p] = 0ull;

    for (int k0 = 0; k0 < 1024; k0 += 16) {
#pragma unroll
        for (int e = 0; e < 2; e++) {
            int id = tid + e * 256;
            int r  = id >> 2;
            int c  = (id & 3) << 2;
            float4 va = *reinterpret_cast<const float4*>(&X[(size_t)(rowBase + r) * 1024 + k0 + c]);
            As[c + 0][r] = va.x; As[c + 1][r] = va.y; As[c + 2][r] = va.z; As[c + 3][r] = va.w;
            float4 vb = *reinterpret_cast<const float4*>(&W[(size_t)(colBase + r) * 1024 + k0 + c]);
            Bs[c + 0][r] = vb.x; Bs[c + 1][r] = vb.y; Bs[c + 2][r] = vb.z; Bs[c + 3][r] = vb.w;
        }
        __syncthreads();
#pragma unroll
        for (int kk = 0; kk < 16; kk++) {
            float4 a0 = *reinterpret_cast<const float4*>(&As[kk][(ty << 2)]);
            float4 a1 = *reinterpret_cast<const float4*>(&As[kk][64 + (ty << 2)]);
            ulonglong2 b0 = *reinterpret_cast<const ulonglong2*>(&Bs[kk][(tx << 2)]);
            ulonglong2 b1 = *reinterpret_cast<const ulonglong2*>(&Bs[kk][64 + (tx << 2)]);
            float a[8] = {a0.x, a0.y, a0.z, a0.w, a1.x, a1.y, a1.z, a1.w};
#pragma unroll
            for (int i = 0; i < 8; i++) {
                unsigned long long aa = bcast2(a[i]);
                ffma2(acc2[i][0], aa, b0.x);
                ffma2(acc2[i][1], aa, b0.y);
                ffma2(acc2[i][2], aa, b1.x);
                ffma2(acc2[i][3], aa, b1.y);
            }
        }
        __syncthreads();
    }

#pragma unroll
    for (int ii = 0; ii < 8; ii++) {
        int r = rowBase + (ii >> 2) * 64 + (ty << 2) + (ii & 3);
#pragma unroll
        for (int jc = 0; jc < 2; jc++) {
            int o0 = colBase + jc * 64 + (tx << 2);
            float4 v;
            unpack2(acc2[ii][jc * 2 + 0], v.x, v.y);
            unpack2(acc2[ii][jc * 2 + 1], v.z, v.w);
            v.x += bias[o0 + 0];
            v.y += bias[o0 + 1];
            v.z += bias[o0 + 2];
            v.w += bias[o0 + 3];
            if (MODE == 0) {
                int bb = r & 3;      // n % B
                int t  = r >> 2;     // n / B
                int hh = o0 >> 6;
                int d  = o0 & 63;
                *reinterpret_cast<float4*>(
                    &Y[((size_t)((bb << 4) + hh) * T + t) * DK + d]) = v;
            } else {
                *reinterpret_cast<float4*>(&Y[(size_t)r * 1024 + o0]) = v;
            }
        }
    }
}

__global__ void __launch_bounds__(256) qkv_kernel(
    const float* __restrict__ q, const float* __restrict__ k, const float* __restrict__ v,
    const float* __restrict__ Wq, const float* __restrict__ Wk, const float* __restrict__ Wv,
    const float* __restrict__ bq, const float* __restrict__ bk, const float* __restrict__ bv)
{
    const float* X; const float* W; const float* bias; float* Y;
    if (blockIdx.z == 0)      { X = q; W = Wq; bias = bq; Y = g_Q; }
    else if (blockIdx.z == 1) { X = k; W = Wk; bias = bk; Y = g_K; }
    else                      { X = v; W = Wv; bias = bv; Y = g_V; }
    gemm_body<0>(X, W, bias, Y);
}

__global__ void __launch_bounds__(256) outproj_kernel(
    const float* __restrict__ Wo, const float* __restrict__ bo, float* __restrict__ out)
{
    gemm_body<1>(g_X2, Wo, bo, out);
}

// ===========================================================================
// Flash attention — FFMA2 packed inner loops (R1-verified structure).
// __launch_bounds__(256, 3): pin >=3 CTAs/SM against register growth.
// ===========================================================================
__global__ void __launch_bounds__(256, 3) attn_kernel()
{
    __shared__ float Qs[DK][64];
    __shared__ float KP[64][64];
    __shared__ float Vs[64][DK];

    const int tid = threadIdx.x;
    const int tx  = tid & 15;
    const int ty  = tid >> 4;
    const int bh  = blockIdx.y;
    const int bb  = bh >> 4;
    const int h   = bh & 15;
    const int q0  = blockIdx.x * 64;

    const float* __restrict__ Qg = g_Q + (size_t)bh * T * DK;
    const float* __restrict__ Kg = g_K + (size_t)bh * T * DK;
    const float* __restrict__ Vg = g_V + (size_t)bh * T * DK;

#pragma unroll
    for (int e = 0; e < 4; e++) {
        int id = tid + e * 256;
        int r  = id >> 4;
        int d  = (id & 15) << 2;
        float4 v = *reinterpret_cast<const float4*>(&Qg[(size_t)(q0 + r) * DK + d]);
        Qs[d + 0][r] = v.x; Qs[d + 1][r] = v.y; Qs[d + 2][r] = v.z; Qs[d + 3][r] = v.w;
    }

    float m_r[4], l_r[4];
    unsigned long long o01[4], o23[4];   // packed O accumulators (cols {0,1},{2,3})
#pragma unroll
    for (int i = 0; i < 4; i++) {
        m_r[i] = -1e30f;
        l_r[i] = 0.0f;
        o01[i] = 0ull;
        o23[i] = 0ull;
    }

    for (int kv0 = 0; kv0 < T; kv0 += 64) {
        __syncthreads();
#pragma unroll
        for (int e = 0; e < 4; e++) {
            int id = tid + e * 256;
            int r  = id >> 4;
            int d  = (id & 15) << 2;
            float4 kv = *reinterpret_cast<const float4*>(&Kg[(size_t)(kv0 + r) * DK + d]);
            KP[d + 0][r] = kv.x; KP[d + 1][r] = kv.y; KP[d + 2][r] = kv.z; KP[d + 3][r] = kv.w;
            float4 vv = *reinterpret_cast<const float4*>(&Vg[(size_t)(kv0 + r) * DK + d]);
            *reinterpret_cast<float4*>(&Vs[r][d]) = vv;
        }
        __syncthreads();

        // S = Q @ K^T, packed along kv
        unsigned long long s01[4] = {0ull, 0ull, 0ull, 0ull};
        unsigned long long s23[4] = {0ull, 0ull, 0ull, 0ull};
#pragma unroll 8
        for (int d = 0; d < DK; d++) {
            float4 a = *reinterpret_cast<const float4*>(&Qs[d][(ty << 2)]);
            ulonglong2 bp = *reinterpret_cast<const ulonglong2*>(&KP[d][(tx << 2)]);
            unsigned long long aa;
            aa = bcast2(a.x); ffma2(s01[0], aa, bp.x); ffma2(s23[0], aa, bp.y);
            aa = bcast2(a.y); ffma2(s01[1], aa, bp.x); ffma2(s23[1], aa, bp.y);
            aa = bcast2(a.z); ffma2(s01[2], aa, bp.x); ffma2(s23[2], aa, bp.y);
            aa = bcast2(a.w); ffma2(s01[3], aa, bp.x); ffma2(s23[3], aa, bp.y);
        }

        // Unpack, mask + scale (reference: mask -> -inf then clip -> -1e8)
        float s[4][4];
#pragma unroll
        for (int i = 0; i < 4; i++) {
            unpack2(s01[i], s[i][0], s[i][1]);
            unpack2(s23[i], s[i][2], s[i][3]);
        }
        uchar4 mk = *reinterpret_cast<const uchar4*>(&g_mask[bb * T + kv0 + (tx << 2)]);
        unsigned char mka[4] = {mk.x, mk.y, mk.z, mk.w};
#pragma unroll
        for (int i = 0; i < 4; i++)
#pragma unroll
            for (int j = 0; j < 4; j++)
                s[i][j] = mka[j] ? -1e8f : s[i][j] * 0.125f;

        // Online softmax over 16 tx lanes
#pragma unroll
        for (int i = 0; i < 4; i++) {
            float mt = fmaxf(fmaxf(s[i][0], s[i][1]), fmaxf(s[i][2], s[i][3]));
#pragma unroll
            for (int w = 1; w < 16; w <<= 1)
                mt = fmaxf(mt, __shfl_xor_sync(0xffffffffu, mt, w));
            float mn   = fmaxf(m_r[i], mt);
            float corr = __expf(m_r[i] - mn);
            m_r[i] = mn;
            float rs = 0.0f;
#pragma unroll
            for (int j = 0; j < 4; j++) {
                float p = __expf(s[i][j] - mn);
                s[i][j] = p;
                rs += p;
            }
#pragma unroll
            for (int w = 1; w < 16; w <<= 1)
                rs += __shfl_xor_sync(0xffffffffu, rs, w);
            l_r[i] = l_r[i] * corr + rs;
            unsigned long long cc = bcast2(corr);
            mul2(o01[i], cc);
            mul2(o23[i], cc);
        }

        __syncthreads();   // all threads done reading KP as K
#pragma unroll
        for (int i = 0; i < 4; i++) {
            float4 pv = make_float4(s[i][0], s[i][1], s[i][2], s[i][3]);
            *reinterpret_cast<float4*>(&KP[(ty << 2) + i][(tx << 2)]) = pv;
        }
        __syncthreads();

        // O += P @ V, packed along d-columns
#pragma unroll 8
        for (int k = 0; k < 64; k++) {
            ulonglong2 bvp = *reinterpret_cast<const ulonglong2*>(&Vs[k][(tx << 2)]);
            unsigned long long aa;
            aa = bcast2(KP[(ty << 2) + 0][k]); ffma2(o01[0], aa, bvp.x); ffma2(o23[0], aa, bvp.y);
            aa = bcast2(KP[(ty << 2) + 1][k]); ffma2(o01[1], aa, bvp.x); ffma2(o23[1], aa, bvp.y);
            aa = bcast2(KP[(ty << 2) + 2][k]); ffma2(o01[2], aa, bvp.x); ffma2(o23[2], aa, bvp.y);
            aa = bcast2(KP[(ty << 2) + 3][k]); ffma2(o01[3], aa, bvp.x); ffma2(o23[3], aa, bvp.y);
        }
    }

    // Epilogue: O /= l, store to X2 rows n = t*B + b, cols h*64 + d
#pragma unroll
    for (int i = 0; i < 4; i++) {
        float inv = 1.0f / l_r[i];
        int t = q0 + (ty << 2) + i;
        float o0, o1, o2, o3;
        unpack2(o01[i], o0, o1);
        unpack2(o23[i], o2, o3);
        float4 ov = make_float4(o0 * inv, o1 * inv, o2 * inv, o3 * inv);
        *reinterpret_cast<float4*>(
            &g_X2[(size_t)(t * B + bb) * C + h * DK + (tx << 2)]) = ov;
    }
}

// ===========================================================================
extern "C" void kernel_launch(void* const* d_in, const int* in_sizes, int n_in,
                              void* d_out, int out_size)
{
    const float* q    = (const float*)d_in[0];
    const float* k    = (const float*)d_in[1];
    const float* v    = (const float*)d_in[2];
    const void*  mask = d_in[3];
    const float* Wq   = (const float*)d_in[4];
    const float* bq   = (const float*)d_in[5];
    const float* Wk   = (const float*)d_in[6];
    const float* bk   = (const float*)d_in[7];
    const float* Wv   = (const float*)d_in[8];
    const float* bv   = (const float*)d_in[9];
    const float* Wo   = (const float*)d_in[10];
    const float* bo   = (const float*)d_in[11];
    float* out = (float*)d_out;

    mask_detect_kernel<<<1, 256>>>((const unsigned char*)mask);
    mask_prep_kernel<<<(B * T + 255) / 256, 256>>>(mask);

    dim3 gqkv(C / 128, NTOK / 128, 3);
    qkv_kernel<<<gqkv, 256>>>(q, k, v, Wq, Wk, Wv, bq, bk, bv);

    attn_kernel<<<dim3(T / 64, BH), 256>>>();

    dim3 gout(C / 128, NTOK / 128);
    outproj_kernel<<<gout, 256>>>(Wo, bo, out);
}